// round 10
// baseline (speedup 1.0000x reference)
#include <cuda_runtime.h>
#include <cstdint>

#define NN 100000
#define NE 3200000
#define FIN 512
#define H   16
#define FOUT 128
#define NC  3

// ---------------- scratch (no allocations allowed) ----------------
__device__ float4 g_P1[NN * 4];    // layer-1 projected RAW (no norm), 16 f/node
__device__ float4 g_agg1[NN * 4];  // layer-1 aggregation target
__device__ float4 g_Q2[NN];        // (relu(...)*ns) @ Wc : 3 floats + pad per node
__device__ float4 g_agg2[NN];      // layer-2 aggregation target (3 floats + pad)
__device__ int    g_deg_out[NN];
__device__ int    g_deg_in[NN];
__device__ float  g_Wc[H * NC];    // W2 @ Wfc  (16x3)
__device__ float  g_bc[NC];        // b2 @ Wfc + bfc
__device__ int    g_is64;

// ---------------- f32x2 packed math helpers ----------------
typedef unsigned long long u64;

__device__ __forceinline__ u64 pack2(float a, float b) {
    u64 r; asm("mov.b64 %0, {%1, %2};" : "=l"(r) : "f"(a), "f"(b)); return r;
}
__device__ __forceinline__ void unpack2(u64 v, float& a, float& b) {
    asm("mov.b64 {%0, %1}, %2;" : "=f"(a), "=f"(b) : "l"(v));
}
__device__ __forceinline__ u64 fma2(u64 a, u64 b, u64 c) {
    u64 d; asm("fma.rn.f32x2 %0, %1, %2, %3;" : "=l"(d) : "l"(a), "l"(b), "l"(c)); return d;
}
__device__ __forceinline__ u64 add2(u64 a, u64 b) {
    u64 d; asm("add.rn.f32x2 %0, %1, %2;" : "=l"(d) : "l"(a), "l"(b)); return d;
}

__device__ __forceinline__ int eidx(const void* p, int e, int is64) {
    if (is64) return (int)__ldcs(((const long long*)p) + e);
    return __ldcs(((const int*)p) + e);
}

__device__ __forceinline__ void red_v4(float4* addr, float x, float y, float z, float w) {
    asm volatile("red.global.add.v4.f32 [%0], {%1, %2, %3, %4};"
                 :: "l"(addr), "f"(x), "f"(y), "f"(z), "f"(w) : "memory");
}

// ---------------- init 0: detect dtype + fused W2@Wfc (1 block) --------------
__global__ void k_init0(const unsigned* __restrict__ srcw,
                        const float* __restrict__ W2, const float* __restrict__ b2,
                        const float* __restrict__ Wfc, const float* __restrict__ bfc) {
    int t = threadIdx.x;
    if (t == 255) {  // int64 idx < 1e5 -> every odd 32-bit word is 0
        int is64 = 1;
        #pragma unroll 1
        for (int j = 0; j < 256; j++) {
            if (srcw[2 * j + 1] != 0u) { is64 = 0; break; }
        }
        g_is64 = is64;
    }
    if (t < H * NC) {
        int k = t / NC, c = t % NC;
        float s = 0.f;
        #pragma unroll 4
        for (int j = 0; j < FOUT; j++) s += W2[k * FOUT + j] * Wfc[j * NC + c];
        g_Wc[t] = s;
    }
    if (t >= 64 && t < 64 + NC) {
        int c = t - 64;
        float s = bfc[c];
        #pragma unroll 4
        for (int j = 0; j < FOUT; j++) s += b2[j] * Wfc[j * NC + c];
        g_bc[c] = s;
    }
}

// ---------------- init 1: zero degrees + agg2 --------------------------------
__global__ void k_init1() {
    int i = blockIdx.x * blockDim.x + threadIdx.x;
    if (i < NN) {
        g_deg_out[i] = 0;
        g_deg_in[i] = 0;
        g_agg2[i] = make_float4(0.f, 0.f, 0.f, 0.f);
    }
}

// ---------------- init 2: zero agg1 ------------------------------------------
__global__ void k_init2() {
    int i = blockIdx.x * blockDim.x + threadIdx.x;
    if (i < NN * 4) g_agg1[i] = make_float4(0.f, 0.f, 0.f, 0.f);
}

// ---------------- lean gemm1: P1 = feat @ W1 (raw, no norm) ------------------
// warp = 4 rows; smem [kk][i] conflict-free (lane-stride 1 u64).
// __launch_bounds__(256,3): 85-reg cap -> 3 blocks/SM (smem 32KB x3 = 96KB OK).
// kk processed in halves of 4 to shrink weight-register live range.
__global__ void __launch_bounds__(256, 3) k_gemm1(const float* __restrict__ feat,
                                                  const float* __restrict__ W1) {
    __shared__ float2 Wp[8 * FIN];  // [kk][i]
    for (int t = threadIdx.x; t < FIN * 8; t += 256) {
        int i = t >> 3, kk = t & 7;
        Wp[kk * FIN + i] = ((const float2*)W1)[t];  // (W1[i][2kk], W1[i][2kk+1])
    }
    __syncthreads();
    const u64* WpU = (const u64*)Wp;

    int warp = threadIdx.x >> 5, lane = threadIdx.x & 31;
    int row0 = (blockIdx.x * 8 + warp) * 4;
    if (row0 >= NN) return;
    bool full = (row0 + 3 < NN);

    u64 acc[4][8];
    #pragma unroll
    for (int r = 0; r < 4; r++)
        #pragma unroll
        for (int kk = 0; kk < 8; kk++) acc[r][kk] = 0ull;

    #pragma unroll
    for (int m = 0; m < 16; m++) {
        int i = lane + 32 * m;
        u64 xx[4];
        if (full) {
            #pragma unroll
            for (int r = 0; r < 4; r++) {
                float xv = __ldcs(feat + (size_t)(row0 + r) * FIN + i);
                xx[r] = pack2(xv, xv);
            }
        } else {
            #pragma unroll
            for (int r = 0; r < 4; r++) {
                float xv = (row0 + r < NN) ? __ldcs(feat + (size_t)(row0 + r) * FIN + i) : 0.f;
                xx[r] = pack2(xv, xv);
            }
        }
        #pragma unroll
        for (int h = 0; h < 2; h++) {
            u64 wk[4];
            #pragma unroll
            for (int q = 0; q < 4; q++) wk[q] = WpU[(4 * h + q) * FIN + i];
            #pragma unroll
            for (int r = 0; r < 4; r++)
                #pragma unroll
                for (int q = 0; q < 4; q++)
                    acc[r][4 * h + q] = fma2(xx[r], wk[q], acc[r][4 * h + q]);
        }
    }

    #pragma unroll
    for (int r = 0; r < 4; r++)
        #pragma unroll
        for (int kk = 0; kk < 8; kk++)
            #pragma unroll
            for (int off = 16; off > 0; off >>= 1)
                acc[r][kk] = add2(acc[r][kk], __shfl_xor_sync(0xffffffffu, acc[r][kk], off));

    if (lane == 0) {
        #pragma unroll
        for (int r = 0; r < 4; r++) {
            int row = row0 + r;
            if (row >= NN) break;
            #pragma unroll
            for (int c = 0; c < 4; c++) {
                float a, b, cc, d;
                unpack2(acc[r][2 * c + 0], a, b);
                unpack2(acc[r][2 * c + 1], cc, d);
                g_P1[row * 4 + c] = make_float4(a, b, cc, d);
            }
        }
    }
}

// ---------------- degrees ----------------
__global__ void k_degree(const void* __restrict__ src, const void* __restrict__ dst) {
    int e = blockIdx.x * blockDim.x + threadIdx.x;
    if (e >= NE) return;
    int is64 = g_is64;
    atomicAdd(&g_deg_out[eidx(src, e, is64)], 1);
    atomicAdd(&g_deg_in[eidx(dst, e, is64)], 1);
}

// ---------------- scatter 1: agg1[dst] += ns[src] * P1[src] ------------------
__global__ void __launch_bounds__(256) k_scatter1(const void* __restrict__ src,
                                                  const void* __restrict__ dst) {
    int e = blockIdx.x * blockDim.x + threadIdx.x;
    if (e >= NE) return;
    int is64 = g_is64;
    int s = eidx(src, e, is64);
    int d = eidx(dst, e, is64);
    float ns = rsqrtf(fmaxf((float)__ldg(&g_deg_out[s]), 1.f));
    const float4* ps = (const float4*)g_P1 + s * 4;
    float4*       pd = g_agg1 + d * 4;
    #pragma unroll
    for (int c = 0; c < 4; c++) {
        float4 v = __ldg(ps + c);
        red_v4(pd + c, v.x * ns, v.y * ns, v.z * ns, v.w * ns);
    }
}

// ---------------- mid: Q2 = (relu(agg1*nd + b1)*ns) @ Wc ---------------------
__global__ void k_mid(const float* __restrict__ b1) {
    int n = blockIdx.x * blockDim.x + threadIdx.x;
    if (n >= NN) return;
    float nd = rsqrtf(fmaxf((float)g_deg_in[n], 1.f));
    float ns = rsqrtf(fmaxf((float)g_deg_out[n], 1.f));
    float o0 = 0.f, o1 = 0.f, o2 = 0.f;
    #pragma unroll
    for (int c = 0; c < 4; c++) {
        float4 a = g_agg1[n * 4 + c];
        float4 b = ((const float4*)b1)[c];
        float h0 = fmaxf(fmaf(a.x, nd, b.x), 0.f) * ns;
        float h1 = fmaxf(fmaf(a.y, nd, b.y), 0.f) * ns;
        float h2 = fmaxf(fmaf(a.z, nd, b.z), 0.f) * ns;
        float h3 = fmaxf(fmaf(a.w, nd, b.w), 0.f) * ns;
        int k = 4 * c;
        o0 = fmaf(h0, g_Wc[(k+0)*NC+0], fmaf(h1, g_Wc[(k+1)*NC+0],
             fmaf(h2, g_Wc[(k+2)*NC+0], fmaf(h3, g_Wc[(k+3)*NC+0], o0))));
        o1 = fmaf(h0, g_Wc[(k+0)*NC+1], fmaf(h1, g_Wc[(k+1)*NC+1],
             fmaf(h2, g_Wc[(k+2)*NC+1], fmaf(h3, g_Wc[(k+3)*NC+1], o1))));
        o2 = fmaf(h0, g_Wc[(k+0)*NC+2], fmaf(h1, g_Wc[(k+1)*NC+2],
             fmaf(h2, g_Wc[(k+2)*NC+2], fmaf(h3, g_Wc[(k+3)*NC+2], o2))));
    }
    g_Q2[n] = make_float4(o0, o1, o2, 0.f);
}

// ---------------- scatter 2: agg2[dst] += Q2[src]  (ONE v4 RED/edge) ---------
__global__ void __launch_bounds__(256) k_scatter2(const void* __restrict__ src,
                                                  const void* __restrict__ dst) {
    int e = blockIdx.x * blockDim.x + threadIdx.x;
    if (e >= NE) return;
    int is64 = g_is64;
    int s = eidx(src, e, is64);
    int d = eidx(dst, e, is64);
    float4 v = __ldg(g_Q2 + s);
    red_v4(g_agg2 + d, v.x, v.y, v.z, v.w);
}

// ---------------- final: out = nd * agg2 + bc -------------------------------
__global__ void k_final(float* __restrict__ out) {
    int n = blockIdx.x * blockDim.x + threadIdx.x;
    if (n >= NN) return;
    float nd = rsqrtf(fmaxf((float)g_deg_in[n], 1.f));
    float4 a = g_agg2[n];
    out[n * 3 + 0] = fmaf(a.x, nd, g_bc[0]);
    out[n * 3 + 1] = fmaf(a.y, nd, g_bc[1]);
    out[n * 3 + 2] = fmaf(a.z, nd, g_bc[2]);
}

// ---------------- launch ----------------
extern "C" void kernel_launch(void* const* d_in, const int* in_sizes, int n_in,
                              void* d_out, int out_size) {
    const float* features = (const float*)d_in[0];
    const void*  src      = d_in[1];
    const void*  dst      = d_in[2];
    const float* W1       = (const float*)d_in[3];
    const float* b1       = (const float*)d_in[4];
    const float* W2       = (const float*)d_in[5];
    const float* b2       = (const float*)d_in[6];
    const float* Wfc      = (const float*)d_in[7];
    const float* bfc      = (const float*)d_in[8];
    float* out = (float*)d_out;

    (void)in_sizes; (void)n_in; (void)out_size;

    const int EB = (NE + 255) / 256;
    const int NB = (NN + 255) / 256;

    k_init0<<<1, 256>>>((const unsigned*)src, W2, b2, Wfc, bfc);   // 1
    k_init1<<<NB, 256>>>();                                        // 2
    k_init2<<<(NN * 4 + 255) / 256, 256>>>();                      // 3
    k_gemm1<<<(NN + 31) / 32, 256>>>(features, W1);                // 4 <- profiled
    k_degree<<<EB, 256>>>(src, dst);                               // 5
    k_scatter1<<<EB, 256>>>(src, dst);                             // 6
    k_mid<<<NB, 256>>>(b1);                                        // 7
    k_scatter2<<<EB, 256>>>(src, dst);                             // 8
    k_final<<<NB, 256>>>(out);                                     // 9
}

// round 11
// speedup vs baseline: 1.2301x; 1.2301x over previous
#include <cuda_runtime.h>
#include <cstdint>

#define NN 100000
#define NE 3200000
#define FIN 512
#define H   16
#define FOUT 128
#define NC  3

// ---------------- scratch (no allocations allowed) ----------------
__device__ float4 g_P1[NN * 4];    // layer-1 projected RAW (no norm), 16 f/node
__device__ float4 g_agg1[NN * 4];  // layer-1 aggregation target
__device__ float4 g_Q2[NN];        // (relu(...)*ns) @ Wc : 3 floats + pad per node
__device__ float4 g_agg2[NN];      // layer-2 aggregation target (3 floats + pad)
__device__ int    g_deg_out[NN];
__device__ int    g_deg_in[NN];
__device__ float  g_Wc[H * NC];    // W2 @ Wfc  (16x3)
__device__ float  g_bc[NC];        // b2 @ Wfc + bfc
__device__ int    g_is64;

// ---------------- f32x2 packed math helpers ----------------
typedef unsigned long long u64;

__device__ __forceinline__ u64 pack2(float a, float b) {
    u64 r; asm("mov.b64 %0, {%1, %2};" : "=l"(r) : "f"(a), "f"(b)); return r;
}
__device__ __forceinline__ void unpack2(u64 v, float& a, float& b) {
    asm("mov.b64 {%0, %1}, %2;" : "=f"(a), "=f"(b) : "l"(v));
}
__device__ __forceinline__ u64 fma2(u64 a, u64 b, u64 c) {
    u64 d; asm("fma.rn.f32x2 %0, %1, %2, %3;" : "=l"(d) : "l"(a), "l"(b), "l"(c)); return d;
}
__device__ __forceinline__ u64 add2(u64 a, u64 b) {
    u64 d; asm("add.rn.f32x2 %0, %1, %2;" : "=l"(d) : "l"(a), "l"(b)); return d;
}

__device__ __forceinline__ int eidx(const void* p, int e, int is64) {
    if (is64) return (int)__ldcs(((const long long*)p) + e);
    return __ldcs(((const int*)p) + e);
}

__device__ __forceinline__ void red_v4(float4* addr, float x, float y, float z, float w) {
    asm volatile("red.global.add.v4.f32 [%0], {%1, %2, %3, %4};"
                 :: "l"(addr), "f"(x), "f"(y), "f"(z), "f"(w) : "memory");
}

// ---------------- init 0: detect dtype + fused W2@Wfc (1 block) --------------
__global__ void k_init0(const unsigned* __restrict__ srcw,
                        const float* __restrict__ W2, const float* __restrict__ b2,
                        const float* __restrict__ Wfc, const float* __restrict__ bfc) {
    int t = threadIdx.x;
    if (t == 255) {  // int64 idx < 1e5 -> every odd 32-bit word is 0
        int is64 = 1;
        #pragma unroll 1
        for (int j = 0; j < 256; j++) {
            if (srcw[2 * j + 1] != 0u) { is64 = 0; break; }
        }
        g_is64 = is64;
    }
    if (t < H * NC) {
        int k = t / NC, c = t % NC;
        float s = 0.f;
        #pragma unroll 4
        for (int j = 0; j < FOUT; j++) s += W2[k * FOUT + j] * Wfc[j * NC + c];
        g_Wc[t] = s;
    }
    if (t >= 64 && t < 64 + NC) {
        int c = t - 64;
        float s = bfc[c];
        #pragma unroll 4
        for (int j = 0; j < FOUT; j++) s += b2[j] * Wfc[j * NC + c];
        g_bc[c] = s;
    }
}

// ---------------- init 1: zero degrees + agg2 --------------------------------
__global__ void k_init1() {
    int i = blockIdx.x * blockDim.x + threadIdx.x;
    if (i < NN) {
        g_deg_out[i] = 0;
        g_deg_in[i] = 0;
        g_agg2[i] = make_float4(0.f, 0.f, 0.f, 0.f);
    }
}

// ---------------- init 2: zero agg1 ------------------------------------------
__global__ void k_init2() {
    int i = blockIdx.x * blockDim.x + threadIdx.x;
    if (i < NN * 4) g_agg1[i] = make_float4(0.f, 0.f, 0.f, 0.f);
}

// ---------------- gemm1, K-output 2-way split --------------------------------
// Pair of blocks (2b, 2b+1) cover the same 32 rows; khalf = blockIdx.x & 1
// selects output cols [8*khalf, 8*khalf+8). Second reader of a feat line hits
// L2. Per warp: 4 rows, lane-split over features, acc 4x4 u64, smem 16 KB.
__global__ void __launch_bounds__(256, 4) k_gemm1(const float* __restrict__ feat,
                                                  const float* __restrict__ W1) {
    __shared__ float2 Wp[4 * FIN];  // [kk_local][i]
    int khalf = blockIdx.x & 1;
    for (int t = threadIdx.x; t < FIN * 4; t += 256) {
        int i = t >> 2, kkl = t & 3;
        Wp[kkl * FIN + i] = ((const float2*)W1)[i * 8 + khalf * 4 + kkl];
    }
    __syncthreads();
    const u64* WpU = (const u64*)Wp;

    int warp = threadIdx.x >> 5, lane = threadIdx.x & 31;
    int row0 = ((blockIdx.x >> 1) * 8 + warp) * 4;
    if (row0 >= NN) return;
    bool full = (row0 + 3 < NN);

    u64 acc[4][4];
    #pragma unroll
    for (int r = 0; r < 4; r++)
        #pragma unroll
        for (int kk = 0; kk < 4; kk++) acc[r][kk] = 0ull;

    #pragma unroll
    for (int m = 0; m < 16; m++) {
        int i = lane + 32 * m;
        u64 xx[4];
        if (full) {
            #pragma unroll
            for (int r = 0; r < 4; r++) {
                float xv = __ldg(feat + (size_t)(row0 + r) * FIN + i);
                xx[r] = pack2(xv, xv);
            }
        } else {
            #pragma unroll
            for (int r = 0; r < 4; r++) {
                float xv = (row0 + r < NN) ? __ldg(feat + (size_t)(row0 + r) * FIN + i) : 0.f;
                xx[r] = pack2(xv, xv);
            }
        }
        u64 wk[4];
        #pragma unroll
        for (int q = 0; q < 4; q++) wk[q] = WpU[q * FIN + i];
        #pragma unroll
        for (int r = 0; r < 4; r++)
            #pragma unroll
            for (int q = 0; q < 4; q++)
                acc[r][q] = fma2(xx[r], wk[q], acc[r][q]);
    }

    #pragma unroll
    for (int r = 0; r < 4; r++)
        #pragma unroll
        for (int kk = 0; kk < 4; kk++)
            #pragma unroll
            for (int off = 16; off > 0; off >>= 1)
                acc[r][kk] = add2(acc[r][kk], __shfl_xor_sync(0xffffffffu, acc[r][kk], off));

    if (lane == 0) {
        #pragma unroll
        for (int r = 0; r < 4; r++) {
            int row = row0 + r;
            if (row >= NN) break;
            #pragma unroll
            for (int c = 0; c < 2; c++) {
                float a, b, cc, d;
                unpack2(acc[r][2 * c + 0], a, b);
                unpack2(acc[r][2 * c + 1], cc, d);
                g_P1[row * 4 + khalf * 2 + c] = make_float4(a, b, cc, d);
            }
        }
    }
}

// ---------------- degrees ----------------
__global__ void k_degree(const void* __restrict__ src, const void* __restrict__ dst) {
    int e = blockIdx.x * blockDim.x + threadIdx.x;
    if (e >= NE) return;
    int is64 = g_is64;
    atomicAdd(&g_deg_out[eidx(src, e, is64)], 1);
    atomicAdd(&g_deg_in[eidx(dst, e, is64)], 1);
}

// ---------------- scatter 1: agg1[dst] += ns[src] * P1[src] ------------------
__global__ void __launch_bounds__(256) k_scatter1(const void* __restrict__ src,
                                                  const void* __restrict__ dst) {
    int e = blockIdx.x * blockDim.x + threadIdx.x;
    if (e >= NE) return;
    int is64 = g_is64;
    int s = eidx(src, e, is64);
    int d = eidx(dst, e, is64);
    float ns = rsqrtf(fmaxf((float)__ldg(&g_deg_out[s]), 1.f));
    const float4* ps = (const float4*)g_P1 + s * 4;
    float4*       pd = g_agg1 + d * 4;
    #pragma unroll
    for (int c = 0; c < 4; c++) {
        float4 v = __ldg(ps + c);
        red_v4(pd + c, v.x * ns, v.y * ns, v.z * ns, v.w * ns);
    }
}

// ---------------- mid: Q2 = (relu(agg1*nd + b1)*ns) @ Wc ---------------------
__global__ void k_mid(const float* __restrict__ b1) {
    int n = blockIdx.x * blockDim.x + threadIdx.x;
    if (n >= NN) return;
    float nd = rsqrtf(fmaxf((float)g_deg_in[n], 1.f));
    float ns = rsqrtf(fmaxf((float)g_deg_out[n], 1.f));
    float o0 = 0.f, o1 = 0.f, o2 = 0.f;
    #pragma unroll
    for (int c = 0; c < 4; c++) {
        float4 a = g_agg1[n * 4 + c];
        float4 b = ((const float4*)b1)[c];
        float h0 = fmaxf(fmaf(a.x, nd, b.x), 0.f) * ns;
        float h1 = fmaxf(fmaf(a.y, nd, b.y), 0.f) * ns;
        float h2 = fmaxf(fmaf(a.z, nd, b.z), 0.f) * ns;
        float h3 = fmaxf(fmaf(a.w, nd, b.w), 0.f) * ns;
        int k = 4 * c;
        o0 = fmaf(h0, g_Wc[(k+0)*NC+0], fmaf(h1, g_Wc[(k+1)*NC+0],
             fmaf(h2, g_Wc[(k+2)*NC+0], fmaf(h3, g_Wc[(k+3)*NC+0], o0))));
        o1 = fmaf(h0, g_Wc[(k+0)*NC+1], fmaf(h1, g_Wc[(k+1)*NC+1],
             fmaf(h2, g_Wc[(k+2)*NC+1], fmaf(h3, g_Wc[(k+3)*NC+1], o1))));
        o2 = fmaf(h0, g_Wc[(k+0)*NC+2], fmaf(h1, g_Wc[(k+1)*NC+2],
             fmaf(h2, g_Wc[(k+2)*NC+2], fmaf(h3, g_Wc[(k+3)*NC+2], o2))));
    }
    g_Q2[n] = make_float4(o0, o1, o2, 0.f);
}

// ---------------- scatter 2: agg2[dst] += Q2[src]  (ONE v4 RED/edge) ---------
__global__ void __launch_bounds__(256) k_scatter2(const void* __restrict__ src,
                                                  const void* __restrict__ dst) {
    int e = blockIdx.x * blockDim.x + threadIdx.x;
    if (e >= NE) return;
    int is64 = g_is64;
    int s = eidx(src, e, is64);
    int d = eidx(dst, e, is64);
    float4 v = __ldg(g_Q2 + s);
    red_v4(g_agg2 + d, v.x, v.y, v.z, v.w);
}

// ---------------- final: out = nd * agg2 + bc -------------------------------
__global__ void k_final(float* __restrict__ out) {
    int n = blockIdx.x * blockDim.x + threadIdx.x;
    if (n >= NN) return;
    float nd = rsqrtf(fmaxf((float)g_deg_in[n], 1.f));
    float4 a = g_agg2[n];
    out[n * 3 + 0] = fmaf(a.x, nd, g_bc[0]);
    out[n * 3 + 1] = fmaf(a.y, nd, g_bc[1]);
    out[n * 3 + 2] = fmaf(a.z, nd, g_bc[2]);
}

// ---------------- launch ----------------
extern "C" void kernel_launch(void* const* d_in, const int* in_sizes, int n_in,
                              void* d_out, int out_size) {
    const float* features = (const float*)d_in[0];
    const void*  src      = d_in[1];
    const void*  dst      = d_in[2];
    const float* W1       = (const float*)d_in[3];
    const float* b1       = (const float*)d_in[4];
    const float* W2       = (const float*)d_in[5];
    const float* b2       = (const float*)d_in[6];
    const float* Wfc      = (const float*)d_in[7];
    const float* bfc      = (const float*)d_in[8];
    float* out = (float*)d_out;

    (void)in_sizes; (void)n_in; (void)out_size;

    const int EB = (NE + 255) / 256;
    const int NB = (NN + 255) / 256;
    const int GB = ((NN + 31) / 32) * 2;  // paired k-half blocks

    k_init0<<<1, 256>>>((const unsigned*)src, W2, b2, Wfc, bfc);   // 1
    k_init1<<<NB, 256>>>();                                        // 2
    k_init2<<<(NN * 4 + 255) / 256, 256>>>();                      // 3
    k_gemm1<<<GB, 256>>>(features, W1);                            // 4 <- profiled
    k_degree<<<EB, 256>>>(src, dst);                               // 5
    k_scatter1<<<EB, 256>>>(src, dst);                             // 6
    k_mid<<<NB, 256>>>(b1);                                        // 7
    k_scatter2<<<EB, 256>>>(src, dst);                             // 8
    k_final<<<NB, 256>>>(out);                                     // 9
}